// round 5
// baseline (speedup 1.0000x reference)
#include <cuda_runtime.h>
#include <cuda_bf16.h>
#include <stdint.h>
#include <math.h>

#define SS 256
#define BB 256
#define HH 1024
#define LL 3
#define NCTA 96
#define NTHR 512
#define KC 64
#define NCHUNK 32
#define BH (BB*HH)
#define GSTRIDE (NCTA*NTHR)
#define KTOT 2048
// SMEM buffer layout (bytes, per buffer): Ah[128][72] Al[128][72] Wh[64][72] Wl[64][72]
#define RSB 144              /* row stride bytes (72 halves) */
#define OFF_AL 18432
#define OFF_WH 36864
#define OFF_WL 46080
#define BUFSZ 55296
#define SMEM_DYN (2*BUFSZ + 16)

typedef unsigned short ush;

// ---------------- device state (static scratch; allocation forbidden) --------
__device__ ush g_h_hi[LL][2][BH];
__device__ ush g_h_lo[LL][2][BH];
__device__ ush g_x_hi[2][BH];
__device__ ush g_x_lo[2][BH];
__device__ ush g_w_hi[LL][HH][KTOT];   // [l][n][k2]: k2<1024 -> W_ih, else W_hh
__device__ ush g_w_lo[LL][HH][KTOT];
__device__ unsigned g_sync[2];

// ---------------- helpers ----------------------------------------------------
static __device__ __forceinline__ unsigned smem_u32(const void* p) {
    unsigned a;
    asm("{ .reg .u64 t; cvta.to.shared.u64 t, %1; cvt.u32.u64 %0, t; }" : "=r"(a) : "l"(p));
    return a;
}
static __device__ __forceinline__ ush f2bf(float f) {
    ush r; asm("cvt.rn.bf16.f32 %0, %1;" : "=h"(r) : "f"(f)); return r;
}
static __device__ __forceinline__ void split2(float f, ush& hi, ush& lo) {
    unsigned u = __float_as_uint(f) & 0xFFFF0000u;
    hi = (ush)(u >> 16);
    lo = f2bf(f - __uint_as_float(u));
}
static __device__ __forceinline__ void cp16(unsigned s, const void* g) {
    asm volatile("cp.async.cg.shared.global [%0], [%1], 16;" :: "r"(s), "l"(g) : "memory");
}
static __device__ __forceinline__ void cp_commit() {
    asm volatile("cp.async.commit_group;" ::: "memory");
}
static __device__ __forceinline__ void cp_wait1() {
    asm volatile("cp.async.wait_group 1;" ::: "memory");
}
static __device__ __forceinline__ void cp_wait0() {
    asm volatile("cp.async.wait_group 0;" ::: "memory");
}
static __device__ __forceinline__ void ldm_x4(unsigned* r, unsigned a) {
    asm volatile("ldmatrix.sync.aligned.m8n8.x4.shared.b16 {%0,%1,%2,%3}, [%4];"
                 : "=r"(r[0]), "=r"(r[1]), "=r"(r[2]), "=r"(r[3]) : "r"(a));
}
static __device__ __forceinline__ void mma16816(float* c, const unsigned* a, const unsigned* b) {
    asm volatile("mma.sync.aligned.m16n8k16.row.col.f32.bf16.bf16.f32 "
                 "{%0,%1,%2,%3}, {%4,%5,%6,%7}, {%8,%9}, {%0,%1,%2,%3};"
                 : "+f"(c[0]), "+f"(c[1]), "+f"(c[2]), "+f"(c[3])
                 : "r"(a[0]), "r"(a[1]), "r"(a[2]), "r"(a[3]), "r"(b[0]), "r"(b[1]));
}

// sense-free grid barrier; all NCTA CTAs co-resident (96 <= 148 SMs)
__device__ __forceinline__ void grid_barrier(unsigned target) {
    __syncthreads();
    __threadfence();
    if (threadIdx.x == 0) {
        unsigned old = atomicAdd(&g_sync[0], 1u);
        if (old == NCTA - 1) {
            atomicExch(&g_sync[0], 0u);
            __threadfence();
            atomicExch(&g_sync[1], target);
        } else {
            while (*((volatile unsigned*)&g_sync[1]) < target) { }
        }
        __threadfence();
    }
    __syncthreads();
}

// issue cp.async loads for chunk c into buffer at sbase (6 x 16B per thread)
static __device__ __forceinline__ void issue_loads(
    int c, unsigned sbase, int tid, int m0,
    const ush* inpHi, const ush* inpLo, const ush* prvHi, const ush* prvLo,
    const ush* wHi, const ush* wLo)
{
    const int ko = (c & 15) * KC;
    const ush* aHi = (c < 16) ? inpHi : prvHi;
    const ush* aLo = (c < 16) ? inpLo : prvLo;
    #pragma unroll
    for (int j = 0; j < 2; j++) {                 // A_hi: 1024 16B chunks
        int cid = tid + 512 * j;
        int row = cid >> 3, seg = cid & 7;
        cp16(sbase + row * RSB + seg * 16, aHi + (size_t)(m0 + row) * HH + ko + seg * 8);
    }
    #pragma unroll
    for (int j = 0; j < 2; j++) {                 // A_lo
        int cid = tid + 512 * j;
        int row = cid >> 3, seg = cid & 7;
        cp16(sbase + OFF_AL + row * RSB + seg * 16, aLo + (size_t)(m0 + row) * HH + ko + seg * 8);
    }
    {                                             // W_hi: 512 chunks
        int row = tid >> 3, seg = tid & 7;
        cp16(sbase + OFF_WH + row * RSB + seg * 16, wHi + (size_t)row * KTOT + c * KC + seg * 8);
        cp16(sbase + OFF_WL + row * RSB + seg * 16, wLo + (size_t)row * KTOT + c * KC + seg * 8);
    }
}

// warp-level compute on one ready chunk buffer; this warp covers kk = kh*2 .. kh*2+1
static __device__ __forceinline__ void compute_chunk(
    unsigned sbase, int lane, int wm, int wn, int kh, float acc[2][4][4])
{
    // lane->addr pattern for A (m16xk16) and B (n16xk16):
    // lanes 0-7: rows 0-7 @ k+0 | 8-15: rows 8-15 @ k+0 | 16-23: rows 0-7 @ k+8 | 24-31: rows 8-15 @ k+8
    const int arow = lane & 15, akoff = (lane >> 4) * 8;
    #pragma unroll
    for (int kk0 = 0; kk0 < 2; kk0++) {
        const int kk = kh * 2 + kk0;
        unsigned ah[2][4], al[2][4], bh[4][2], bl[4][2];
        #pragma unroll
        for (int mb = 0; mb < 2; mb++) {
            unsigned addr = sbase + (wm + mb * 16 + arow) * RSB + (kk * 16 + akoff) * 2;
            ldm_x4(ah[mb], addr);
            ldm_x4(al[mb], addr + OFF_AL);
        }
        #pragma unroll
        for (int g = 0; g < 2; g++) {
            // non-trans ldmatrix on W[n][k] -> col-major B frag:
            // r0 = n-blk0 k-lo, r1 = n-blk1 k-lo, r2 = n-blk0 k-hi, r3 = n-blk1 k-hi
            unsigned addr = sbase + OFF_WH + (wn + g * 16 + arow) * RSB + (kk * 16 + akoff) * 2;
            unsigned r[4];
            ldm_x4(r, addr);
            bh[2 * g][0] = r[0]; bh[2 * g][1] = r[2];
            bh[2 * g + 1][0] = r[1]; bh[2 * g + 1][1] = r[3];
            ldm_x4(r, addr + (OFF_WL - OFF_WH));
            bl[2 * g][0] = r[0]; bl[2 * g][1] = r[2];
            bl[2 * g + 1][0] = r[1]; bl[2 * g + 1][1] = r[3];
        }
        #pragma unroll
        for (int mb = 0; mb < 2; mb++)
            #pragma unroll
            for (int nb = 0; nb < 4; nb++) {
                mma16816(acc[mb][nb], ah[mb], bh[nb]);
                mma16816(acc[mb][nb], ah[mb], bl[nb]);
                mma16816(acc[mb][nb], al[mb], bh[nb]);
            }
    }
}

// ---------------- persistent kernel ------------------------------------------
__global__ void __launch_bounds__(NTHR, 1) rnn_mma(
    const float* __restrict__ x, const float* __restrict__ h0,
    const float* __restrict__ W_ih, const float* __restrict__ W_hh,
    const float* __restrict__ b_ih, const float* __restrict__ b_hh,
    float* __restrict__ out)
{
    extern __shared__ __align__(16) char dsm[];
    __shared__ float s_bias[64];

    const int tid = threadIdx.x;
    const int lane = tid & 31;
    const int w = tid >> 5;
    const int kh = w >> 3;               // k-half: 0 -> kk 0-1, 1 -> kk 2-3
    const int wi = w & 7;                // output sub-tile id (shared by warp pair)
    const int wm = (wi >> 1) * 32;       // warp m-offset in tile
    const int wn = (wi & 1) * 32;        // warp n-offset in tile
    const int cta = blockIdx.x;
    const int l = cta / 32;              // layer group
    const int id = cta % 32;
    const int m0 = (id & 1) * 128;
    const int n0 = (id >> 1) * 64;

    const unsigned dynu = smem_u32(dsm);
    float* red = (float*)dsm;            // 32KB reduction area (reused, post-drain)

    if (tid < 64) s_bias[tid] = b_ih[l * HH + n0 + tid] + b_hh[l * HH + n0 + tid];

    // ---- prepass: split W (ih||hh packed), h0 (parity 1), x_0 (slot 0) ------
    for (int idx = cta * NTHR + tid; idx < LL * HH * KTOT; idx += GSTRIDE) {
        int l2 = idx >> 21;
        int rem = idx & ((1 << 21) - 1);
        int n = rem >> 11;
        int k2 = rem & (KTOT - 1);
        float f = (k2 < HH) ? W_ih[((size_t)l2 * HH + n) * HH + k2]
                            : W_hh[((size_t)l2 * HH + n) * HH + (k2 - HH)];
        split2(f, ((ush*)g_w_hi)[idx], ((ush*)g_w_lo)[idx]);
    }
    for (int idx = cta * NTHR + tid; idx < LL * BH; idx += GSTRIDE) {
        int l2 = idx >> 18;
        int i = idx & (BH - 1);
        split2(h0[idx], g_h_hi[l2][1][i], g_h_lo[l2][1][i]);
    }
    for (int idx = cta * NTHR + tid; idx < BH; idx += GSTRIDE)
        split2(x[idx], g_x_hi[0][idx], g_x_lo[0][idx]);

    grid_barrier(1u);
    unsigned bt = 2;

    for (int d = 0; d < SS + LL - 1; d++) {
        const int t = d - l;
        if (t >= 0 && t < SS) {
            const ush* inpHi = (l == 0) ? g_x_hi[t & 1] : g_h_hi[l - 1][t & 1];
            const ush* inpLo = (l == 0) ? g_x_lo[t & 1] : g_h_lo[l - 1][t & 1];
            const ush* prvHi = g_h_hi[l][(t & 1) ^ 1];
            const ush* prvLo = g_h_lo[l][(t & 1) ^ 1];
            const ush* wHi = &g_w_hi[l][n0][0];
            const ush* wLo = &g_w_lo[l][n0][0];

            float acc[2][4][4];
            #pragma unroll
            for (int a = 0; a < 2; a++)
                #pragma unroll
                for (int b = 0; b < 4; b++)
                    #pragma unroll
                    for (int cc = 0; cc < 4; cc++) acc[a][b][cc] = 0.f;

            issue_loads(0, dynu, tid, m0, inpHi, inpLo, prvHi, prvLo, wHi, wLo);
            cp_commit();
            for (int c = 0; c < NCHUNK; c++) {
                if (c + 1 < NCHUNK) {
                    issue_loads(c + 1, dynu + ((c + 1) & 1) * BUFSZ, tid, m0,
                                inpHi, inpLo, prvHi, prvLo, wHi, wLo);
                    cp_commit();
                    cp_wait1();
                } else {
                    cp_wait0();
                }
                __syncthreads();
                compute_chunk(dynu + (c & 1) * BUFSZ, lane, wm, wn, kh, acc);
                __syncthreads();
            }

            // ---- merge k-halves: high warps publish, low warps add ----------
            if (kh == 1) {
                #pragma unroll
                for (int mb = 0; mb < 2; mb++)
                    #pragma unroll
                    for (int nb = 0; nb < 4; nb++)
                        #pragma unroll
                        for (int cc = 0; cc < 4; cc++)
                            red[wi * 1024 + ((mb * 4 + nb) * 4 + cc) * 32 + lane] = acc[mb][nb][cc];
            }
            __syncthreads();

            if (kh == 0) {
                #pragma unroll
                for (int mb = 0; mb < 2; mb++)
                    #pragma unroll
                    for (int nb = 0; nb < 4; nb++)
                        #pragma unroll
                        for (int cc = 0; cc < 4; cc++)
                            acc[mb][nb][cc] += red[wi * 1024 + ((mb * 4 + nb) * 4 + cc) * 32 + lane];

                // ---- epilogue: bias + tanh + split/store --------------------
                ush* hiBase = g_h_hi[l][t & 1];
                ush* loBase = g_h_lo[l][t & 1];
                float* ybase = out + (size_t)t * BH;
                float* hbase = out + (size_t)SS * BH + (size_t)l * BH;
                const bool wy = (l == LL - 1);
                const bool wh2 = (t == SS - 1);
                #pragma unroll
                for (int mb = 0; mb < 2; mb++) {
                    #pragma unroll
                    for (int rh = 0; rh < 2; rh++) {
                        const int gm = m0 + wm + mb * 16 + rh * 8 + (lane >> 2);
                        #pragma unroll
                        for (int nb = 0; nb < 4; nb++) {
                            const int cl = wn + nb * 8 + 2 * (lane & 3);   // 0..63
                            float p0 = acc[mb][nb][rh * 2 + 0] + s_bias[cl];
                            float p1 = acc[mb][nb][rh * 2 + 1] + s_bias[cl + 1];
                            float f0 = tanhf(p0);
                            float f1 = tanhf(p1);
                            ush h0v, l0v, h1v, l1v;
                            split2(f0, h0v, l0v);
                            split2(f1, h1v, l1v);
                            const size_t off = (size_t)gm * HH + n0 + cl;
                            *(unsigned*)(hiBase + off) = (unsigned)h0v | ((unsigned)h1v << 16);
                            *(unsigned*)(loBase + off) = (unsigned)l0v | ((unsigned)l1v << 16);
                            if (wy) *(float2*)(ybase + off) = make_float2(f0, f1);
                            if (wh2) *(float2*)(hbase + off) = make_float2(f0, f1);
                        }
                    }
                }
            }
        }
        // cooperative split of x_{d+1} into the other ring slot
        const int tn = d + 1;
        if (tn < SS) {
            const int sl = tn & 1;
            for (int i = cta * NTHR + tid; i < BH; i += GSTRIDE)
                split2(x[(size_t)tn * BH + i], g_x_hi[sl][i], g_x_lo[sl][i]);
        }
        grid_barrier(bt++);
    }
}

extern "C" void kernel_launch(void* const* d_in, const int* in_sizes, int n_in,
                              void* d_out, int out_size) {
    const float* x    = (const float*)d_in[0];
    const float* h0   = (const float*)d_in[1];
    const float* W_ih = (const float*)d_in[2];
    const float* W_hh = (const float*)d_in[3];
    const float* b_ih = (const float*)d_in[4];
    const float* b_hh = (const float*)d_in[5];
    float* out = (float*)d_out;

    cudaFuncSetAttribute(rnn_mma, cudaFuncAttributeMaxDynamicSharedMemorySize, SMEM_DYN);
    void* sp = nullptr;
    cudaGetSymbolAddress(&sp, g_sync);
    cudaMemsetAsync(sp, 0, sizeof(unsigned) * 2);
    rnn_mma<<<NCTA, NTHR, SMEM_DYN>>>(x, h0, W_ih, W_hh, b_ih, b_hh, out);
}

// round 6
// speedup vs baseline: 1.0728x; 1.0728x over previous
#include <cuda_runtime.h>
#include <cuda_bf16.h>
#include <stdint.h>
#include <math.h>

#define SS 256
#define BB 256
#define HH 1024
#define LL 3
#define NCTA 96
#define NTHR 512
#define KC 64
#define NCHUNK 32
#define BH (BB*HH)
#define GSTRIDE (NCTA*NTHR)
#define KTOT 2048
// SMEM buffer layout (bytes, per buffer): Ah[128][72] Al[128][72] Wh[64][72] Wl[64][72]
#define RSB 144              /* row stride bytes (72 halves) */
#define OFF_AL 18432
#define OFF_WH 36864
#define OFF_WL 46080
#define BUFSZ 55296
#define NSTAGE 3
#define SMEM_DYN (NSTAGE*BUFSZ + 16)

typedef unsigned short ush;

// ---------------- device state (static scratch; allocation forbidden) --------
__device__ ush g_h_hi[LL][2][BH];
__device__ ush g_h_lo[LL][2][BH];
__device__ ush g_x_hi[2][BH];
__device__ ush g_x_lo[2][BH];
__device__ ush g_w_hi[LL][HH][KTOT];   // [l][n][k2]: k2<1024 -> W_ih, else W_hh
__device__ ush g_w_lo[LL][HH][KTOT];
__device__ unsigned g_sync[2];

// ---------------- helpers ----------------------------------------------------
static __device__ __forceinline__ unsigned smem_u32(const void* p) {
    unsigned a;
    asm("{ .reg .u64 t; cvta.to.shared.u64 t, %1; cvt.u32.u64 %0, t; }" : "=r"(a) : "l"(p));
    return a;
}
static __device__ __forceinline__ ush f2bf(float f) {
    ush r; asm("cvt.rn.bf16.f32 %0, %1;" : "=h"(r) : "f"(f)); return r;
}
static __device__ __forceinline__ void split2(float f, ush& hi, ush& lo) {
    unsigned u = __float_as_uint(f) & 0xFFFF0000u;
    hi = (ush)(u >> 16);
    lo = f2bf(f - __uint_as_float(u));
}
static __device__ __forceinline__ void cp16(unsigned s, const void* g) {
    asm volatile("cp.async.cg.shared.global [%0], [%1], 16;" :: "r"(s), "l"(g) : "memory");
}
static __device__ __forceinline__ void cp_commit() {
    asm volatile("cp.async.commit_group;" ::: "memory");
}
static __device__ __forceinline__ void cp_wait1() {
    asm volatile("cp.async.wait_group 1;" ::: "memory");
}
static __device__ __forceinline__ void cp_wait0() {
    asm volatile("cp.async.wait_group 0;" ::: "memory");
}
static __device__ __forceinline__ void ldm_x4(unsigned* r, unsigned a) {
    asm volatile("ldmatrix.sync.aligned.m8n8.x4.shared.b16 {%0,%1,%2,%3}, [%4];"
                 : "=r"(r[0]), "=r"(r[1]), "=r"(r[2]), "=r"(r[3]) : "r"(a));
}
static __device__ __forceinline__ void mma16816(float* c, const unsigned* a, const unsigned* b) {
    asm volatile("mma.sync.aligned.m16n8k16.row.col.f32.bf16.bf16.f32 "
                 "{%0,%1,%2,%3}, {%4,%5,%6,%7}, {%8,%9}, {%0,%1,%2,%3};"
                 : "+f"(c[0]), "+f"(c[1]), "+f"(c[2]), "+f"(c[3])
                 : "r"(a[0]), "r"(a[1]), "r"(a[2]), "r"(a[3]), "r"(b[0]), "r"(b[1]));
}

// sense-free grid barrier; all NCTA CTAs co-resident (96 <= 148 SMs)
__device__ __forceinline__ void grid_barrier(unsigned target) {
    __syncthreads();
    __threadfence();
    if (threadIdx.x == 0) {
        unsigned old = atomicAdd(&g_sync[0], 1u);
        if (old == NCTA - 1) {
            atomicExch(&g_sync[0], 0u);
            __threadfence();
            atomicExch(&g_sync[1], target);
        } else {
            while (*((volatile unsigned*)&g_sync[1]) < target) { }
        }
        __threadfence();
    }
    __syncthreads();
}

// issue cp.async loads for chunk c into buffer at sbase (6 x 16B per thread)
static __device__ __forceinline__ void issue_loads(
    int c, unsigned sbase, int tid, int m0,
    const ush* inpHi, const ush* inpLo, const ush* prvHi, const ush* prvLo,
    const ush* wHi, const ush* wLo)
{
    const int ko = (c & 15) * KC;
    const ush* aHi = (c < 16) ? inpHi : prvHi;
    const ush* aLo = (c < 16) ? inpLo : prvLo;
    #pragma unroll
    for (int j = 0; j < 2; j++) {                 // A_hi: 1024 16B chunks
        int cid = tid + 512 * j;
        int row = cid >> 3, seg = cid & 7;
        cp16(sbase + row * RSB + seg * 16, aHi + (size_t)(m0 + row) * HH + ko + seg * 8);
    }
    #pragma unroll
    for (int j = 0; j < 2; j++) {                 // A_lo
        int cid = tid + 512 * j;
        int row = cid >> 3, seg = cid & 7;
        cp16(sbase + OFF_AL + row * RSB + seg * 16, aLo + (size_t)(m0 + row) * HH + ko + seg * 8);
    }
    {                                             // W_hi + W_lo: 512 chunks each
        int row = tid >> 3, seg = tid & 7;
        cp16(sbase + OFF_WH + row * RSB + seg * 16, wHi + (size_t)row * KTOT + c * KC + seg * 8);
        cp16(sbase + OFF_WL + row * RSB + seg * 16, wLo + (size_t)row * KTOT + c * KC + seg * 8);
    }
}

// warp-level compute on one ready chunk buffer; this warp covers kk = kh*2 .. kh*2+1
static __device__ __forceinline__ void compute_chunk(
    unsigned sbase, int lane, int wm, int wn, int kh, float acc[2][4][4])
{
    // lane->addr pattern for A (m16xk16) and B (n16xk16):
    // lanes 0-7: rows 0-7 @ k+0 | 8-15: rows 8-15 @ k+0 | 16-23: rows 0-7 @ k+8 | 24-31: rows 8-15 @ k+8
    const int arow = lane & 15, akoff = (lane >> 4) * 8;
    #pragma unroll
    for (int kk0 = 0; kk0 < 2; kk0++) {
        const int kk = kh * 2 + kk0;
        unsigned ah[2][4], al[2][4], bh[4][2], bl[4][2];
        #pragma unroll
        for (int mb = 0; mb < 2; mb++) {
            unsigned addr = sbase + (wm + mb * 16 + arow) * RSB + (kk * 16 + akoff) * 2;
            ldm_x4(ah[mb], addr);
            ldm_x4(al[mb], addr + OFF_AL);
        }
        #pragma unroll
        for (int g = 0; g < 2; g++) {
            // non-trans ldmatrix on W[n][k] -> col-major B frag:
            // r0 = n-blk0 k-lo, r1 = n-blk1 k-lo, r2 = n-blk0 k-hi, r3 = n-blk1 k-hi
            unsigned addr = sbase + OFF_WH + (wn + g * 16 + arow) * RSB + (kk * 16 + akoff) * 2;
            unsigned r[4];
            ldm_x4(r, addr);
            bh[2 * g][0] = r[0]; bh[2 * g][1] = r[2];
            bh[2 * g + 1][0] = r[1]; bh[2 * g + 1][1] = r[3];
            ldm_x4(r, addr + (OFF_WL - OFF_WH));
            bl[2 * g][0] = r[0]; bl[2 * g][1] = r[2];
            bl[2 * g + 1][0] = r[1]; bl[2 * g + 1][1] = r[3];
        }
        #pragma unroll
        for (int mb = 0; mb < 2; mb++)
            #pragma unroll
            for (int nb = 0; nb < 4; nb++) {
                mma16816(acc[mb][nb], ah[mb], bh[nb]);
                mma16816(acc[mb][nb], ah[mb], bl[nb]);
                mma16816(acc[mb][nb], al[mb], bh[nb]);
            }
    }
}

// ---------------- persistent kernel ------------------------------------------
__global__ void __launch_bounds__(NTHR, 1) rnn_mma(
    const float* __restrict__ x, const float* __restrict__ h0,
    const float* __restrict__ W_ih, const float* __restrict__ W_hh,
    const float* __restrict__ b_ih, const float* __restrict__ b_hh,
    float* __restrict__ out)
{
    extern __shared__ __align__(16) char dsm[];
    __shared__ float s_bias[64];

    const int tid = threadIdx.x;
    const int lane = tid & 31;
    const int w = tid >> 5;
    const int kh = w >> 3;               // k-half: 0 -> kk 0-1, 1 -> kk 2-3
    const int wi = w & 7;                // output sub-tile id (shared by warp pair)
    const int wm = (wi >> 1) * 32;       // warp m-offset in tile
    const int wn = (wi & 1) * 32;        // warp n-offset in tile
    const int cta = blockIdx.x;
    const int l = cta / 32;              // layer group
    const int id = cta % 32;
    const int m0 = (id & 1) * 128;
    const int n0 = (id >> 1) * 64;

    const unsigned dynu = smem_u32(dsm);
    float* red = (float*)dsm;            // 32KB reduction area (reused, post-drain)

    if (tid < 64) s_bias[tid] = b_ih[l * HH + n0 + tid] + b_hh[l * HH + n0 + tid];

    // ---- prepass: split W (ih||hh packed), h0 (parity 1), x_0 (slot 0) ------
    for (int idx = cta * NTHR + tid; idx < LL * HH * KTOT; idx += GSTRIDE) {
        int l2 = idx >> 21;
        int rem = idx & ((1 << 21) - 1);
        int n = rem >> 11;
        int k2 = rem & (KTOT - 1);
        float f = (k2 < HH) ? W_ih[((size_t)l2 * HH + n) * HH + k2]
                            : W_hh[((size_t)l2 * HH + n) * HH + (k2 - HH)];
        split2(f, ((ush*)g_w_hi)[idx], ((ush*)g_w_lo)[idx]);
    }
    for (int idx = cta * NTHR + tid; idx < LL * BH; idx += GSTRIDE) {
        int l2 = idx >> 18;
        int i = idx & (BH - 1);
        split2(h0[idx], g_h_hi[l2][1][i], g_h_lo[l2][1][i]);
    }
    for (int idx = cta * NTHR + tid; idx < BH; idx += GSTRIDE)
        split2(x[idx], g_x_hi[0][idx], g_x_lo[0][idx]);

    grid_barrier(1u);
    unsigned bt = 2;

    for (int d = 0; d < SS + LL - 1; d++) {
        const int t = d - l;
        if (t >= 0 && t < SS) {
            const ush* inpHi = (l == 0) ? g_x_hi[t & 1] : g_h_hi[l - 1][t & 1];
            const ush* inpLo = (l == 0) ? g_x_lo[t & 1] : g_h_lo[l - 1][t & 1];
            const ush* prvHi = g_h_hi[l][(t & 1) ^ 1];
            const ush* prvLo = g_h_lo[l][(t & 1) ^ 1];
            const ush* wHi = &g_w_hi[l][n0][0];
            const ush* wLo = &g_w_lo[l][n0][0];

            float acc[2][4][4];
            #pragma unroll
            for (int a = 0; a < 2; a++)
                #pragma unroll
                for (int b = 0; b < 4; b++)
                    #pragma unroll
                    for (int cc = 0; cc < 4; cc++) acc[a][b][cc] = 0.f;

            // ---- 3-stage cp.async ring, ONE barrier per chunk ----------------
            // invariant at top of iter c: groups <= c-1 complete after wait,
            // writes for chunk c+2 go to buffer (c+2)%3 == (c-1)%3, whose readers
            // (chunk c-1) are proven done by this iteration's __syncthreads().
            issue_loads(0, dynu + 0 * BUFSZ, tid, m0, inpHi, inpLo, prvHi, prvLo, wHi, wLo);
            cp_commit();
            issue_loads(1, dynu + 1 * BUFSZ, tid, m0, inpHi, inpLo, prvHi, prvLo, wHi, wLo);
            cp_commit();
            int bufc = 0;                 // buffer index of chunk c (c % 3)
            for (int c = 0; c < NCHUNK; c++) {
                if (c == NCHUNK - 1) cp_wait0(); else cp_wait1();
                __syncthreads();
                if (c + 2 < NCHUNK) {
                    int bufn = bufc + 2 - ((bufc + 2 >= NSTAGE) ? NSTAGE : 0);
                    issue_loads(c + 2, dynu + bufn * BUFSZ, tid, m0,
                                inpHi, inpLo, prvHi, prvLo, wHi, wLo);
                    cp_commit();
                }
                compute_chunk(dynu + bufc * BUFSZ, lane, wm, wn, kh, acc);
                if (++bufc == NSTAGE) bufc = 0;
            }
            __syncthreads();   // all compute done before reduction reuses buffer 0

            // ---- merge k-halves: high warps publish, low warps add ----------
            if (kh == 1) {
                #pragma unroll
                for (int mb = 0; mb < 2; mb++)
                    #pragma unroll
                    for (int nb = 0; nb < 4; nb++)
                        #pragma unroll
                        for (int cc = 0; cc < 4; cc++)
                            red[wi * 1024 + ((mb * 4 + nb) * 4 + cc) * 32 + lane] = acc[mb][nb][cc];
            }
            __syncthreads();

            if (kh == 0) {
                #pragma unroll
                for (int mb = 0; mb < 2; mb++)
                    #pragma unroll
                    for (int nb = 0; nb < 4; nb++)
                        #pragma unroll
                        for (int cc = 0; cc < 4; cc++)
                            acc[mb][nb][cc] += red[wi * 1024 + ((mb * 4 + nb) * 4 + cc) * 32 + lane];

                // ---- epilogue: bias + tanh + split/store --------------------
                ush* hiBase = g_h_hi[l][t & 1];
                ush* loBase = g_h_lo[l][t & 1];
                float* ybase = out + (size_t)t * BH;
                float* hbase = out + (size_t)SS * BH + (size_t)l * BH;
                const bool wy = (l == LL - 1);
                const bool wh2 = (t == SS - 1);
                #pragma unroll
                for (int mb = 0; mb < 2; mb++) {
                    #pragma unroll
                    for (int rh = 0; rh < 2; rh++) {
                        const int gm = m0 + wm + mb * 16 + rh * 8 + (lane >> 2);
                        #pragma unroll
                        for (int nb = 0; nb < 4; nb++) {
                            const int cl = wn + nb * 8 + 2 * (lane & 3);   // 0..63
                            float p0 = acc[mb][nb][rh * 2 + 0] + s_bias[cl];
                            float p1 = acc[mb][nb][rh * 2 + 1] + s_bias[cl + 1];
                            float f0 = tanhf(p0);
                            float f1 = tanhf(p1);
                            ush h0v, l0v, h1v, l1v;
                            split2(f0, h0v, l0v);
                            split2(f1, h1v, l1v);
                            const size_t off = (size_t)gm * HH + n0 + cl;
                            *(unsigned*)(hiBase + off) = (unsigned)h0v | ((unsigned)h1v << 16);
                            *(unsigned*)(loBase + off) = (unsigned)l0v | ((unsigned)l1v << 16);
                            if (wy) *(float2*)(ybase + off) = make_float2(f0, f1);
                            if (wh2) *(float2*)(hbase + off) = make_float2(f0, f1);
                        }
                    }
                }
            }
        }
        // cooperative split of x_{d+1} into the other ring slot
        const int tn = d + 1;
        if (tn < SS) {
            const int sl = tn & 1;
            for (int i = cta * NTHR + tid; i < BH; i += GSTRIDE)
                split2(x[(size_t)tn * BH + i], g_x_hi[sl][i], g_x_lo[sl][i]);
        }
        grid_barrier(bt++);
    }
}

extern "C" void kernel_launch(void* const* d_in, const int* in_sizes, int n_in,
                              void* d_out, int out_size) {
    const float* x    = (const float*)d_in[0];
    const float* h0   = (const float*)d_in[1];
    const float* W_ih = (const float*)d_in[2];
    const float* W_hh = (const float*)d_in[3];
    const float* b_ih = (const float*)d_in[4];
    const float* b_hh = (const float*)d_in[5];
    float* out = (float*)d_out;

    cudaFuncSetAttribute(rnn_mma, cudaFuncAttributeMaxDynamicSharedMemorySize, SMEM_DYN);
    void* sp = nullptr;
    cudaGetSymbolAddress(&sp, g_sync);
    cudaMemsetAsync(sp, 0, sizeof(unsigned) * 2);
    rnn_mma<<<NCTA, NTHR, SMEM_DYN>>>(x, h0, W_ih, W_hh, b_ih, b_hh, out);
}

// round 10
// speedup vs baseline: 1.3551x; 1.2631x over previous
#include <cuda_runtime.h>
#include <cuda_bf16.h>
#include <stdint.h>
#include <math.h>

#define SS 256
#define BB 256
#define HH 1024
#define LL 3
#define NCTA 144
#define NTHR 256
#define KC 64
#define NCHUNK 32
#define BH (BB*HH)
#define GSTRIDE (NCTA*NTHR)
#define KTOT 2048
// per ring buffer: A[128][72] then W[128][72] (halves), row stride 144B
#define RSB 144
#define OFF_W 18432
#define BUFSZ 36864
#define NSTAGE 3
#define SMEM_DYN (NSTAGE*BUFSZ + 16)

typedef unsigned short ush;

// ---------------- device state (static scratch; allocation forbidden) --------
__device__ ush g_h_hi[LL][2][BH];
__device__ ush g_h_lo[LL][2][BH];
__device__ ush g_x_hi[2][BH];
__device__ ush g_x_lo[2][BH];
__device__ ush g_w_hi[LL][HH][KTOT];   // [l][n][k2]: k2<1024 -> W_ih, else W_hh
__device__ ush g_w_lo[LL][HH][KTOT];
__device__ float g_part[LL][3][BH];    // per-stage per-product fp32 partials
__device__ float g_bias[LL][HH];
__device__ unsigned g_sync[2];

// ---------------- helpers ----------------------------------------------------
static __device__ __forceinline__ unsigned smem_u32(const void* p) {
    unsigned a;
    asm("{ .reg .u64 t; cvta.to.shared.u64 t, %1; cvt.u32.u64 %0, t; }" : "=r"(a) : "l"(p));
    return a;
}
static __device__ __forceinline__ ush f2bf(float f) {
    ush r; asm("cvt.rn.bf16.f32 %0, %1;" : "=h"(r) : "f"(f)); return r;
}
static __device__ __forceinline__ void split2(float f, ush& hi, ush& lo) {
    unsigned u = __float_as_uint(f) & 0xFFFF0000u;
    hi = (ush)(u >> 16);
    lo = f2bf(f - __uint_as_float(u));
}
static __device__ __forceinline__ void cp16(unsigned s, const void* g) {
    asm volatile("cp.async.cg.shared.global [%0], [%1], 16;" :: "r"(s), "l"(g) : "memory");
}
static __device__ __forceinline__ void cp_commit() {
    asm volatile("cp.async.commit_group;" ::: "memory");
}
static __device__ __forceinline__ void cp_wait1() {
    asm volatile("cp.async.wait_group 1;" ::: "memory");
}
static __device__ __forceinline__ void cp_wait0() {
    asm volatile("cp.async.wait_group 0;" ::: "memory");
}
static __device__ __forceinline__ void ldm_x4(unsigned* r, unsigned a) {
    asm volatile("ldmatrix.sync.aligned.m8n8.x4.shared.b16 {%0,%1,%2,%3}, [%4];"
                 : "=r"(r[0]), "=r"(r[1]), "=r"(r[2]), "=r"(r[3]) : "r"(a));
}
static __device__ __forceinline__ void mma16816(float* c, const unsigned* a, const unsigned* b) {
    asm volatile("mma.sync.aligned.m16n8k16.row.col.f32.bf16.bf16.f32 "
                 "{%0,%1,%2,%3}, {%4,%5,%6,%7}, {%8,%9}, {%0,%1,%2,%3};"
                 : "+f"(c[0]), "+f"(c[1]), "+f"(c[2]), "+f"(c[3])
                 : "r"(a[0]), "r"(a[1]), "r"(a[2]), "r"(a[3]), "r"(b[0]), "r"(b[1]));
}

// sense-free grid barrier; all NCTA CTAs co-resident (144 <= 148 SMs)
__device__ __forceinline__ void grid_barrier(unsigned target) {
    __syncthreads();
    __threadfence();
    if (threadIdx.x == 0) {
        unsigned old = atomicAdd(&g_sync[0], 1u);
        if (old == NCTA - 1) {
            atomicExch(&g_sync[0], 0u);
            __threadfence();
            atomicExch(&g_sync[1], target);
        } else {
            while (*((volatile unsigned*)&g_sync[1]) < target) { }
        }
        __threadfence();
    }
    __syncthreads();
}

// issue cp.async for chunk c: A-component tile [128][64], W-component tile [128][64]
static __device__ __forceinline__ void issue_loads(
    int c, unsigned sbase, int tid, int m0, int n0,
    const ush* inpC, const ush* prvC, const ush* wC)
{
    const int ko = (c & 15) * KC;
    const ush* aC = (c < 16) ? inpC : prvC;
    #pragma unroll
    for (int j = 0; j < 4; j++) {                 // A: 1024 16B chunks
        int cid = tid + 256 * j;
        int row = cid >> 3, seg = cid & 7;
        cp16(sbase + row * RSB + seg * 16, aC + (size_t)(m0 + row) * HH + ko + seg * 8);
    }
    #pragma unroll
    for (int j = 0; j < 4; j++) {                 // W: 1024 16B chunks
        int cid = tid + 256 * j;
        int row = cid >> 3, seg = cid & 7;
        cp16(sbase + OFF_W + row * RSB + seg * 16, wC + (size_t)(n0 + row) * KTOT + c * KC + seg * 8);
    }
}

// warp computes its 32x64 sub-tile of the 128x128 CTA tile for one 64-K chunk
static __device__ __forceinline__ void compute_chunk(
    unsigned sbase, int lane, int wm, int wn, float acc[2][8][4])
{
    // lane->addr: lanes 0-7 rows0-7@k0 | 8-15 rows8-15@k0 | 16-23 rows0-7@k8 | 24-31 rows8-15@k8
    const int arow = lane & 15, akoff = (lane >> 4) * 8;
    #pragma unroll
    for (int kk = 0; kk < 4; kk++) {
        unsigned a[2][4], b[8][2];
        #pragma unroll
        for (int mb = 0; mb < 2; mb++)
            ldm_x4(a[mb], sbase + (wm + mb * 16 + arow) * RSB + (kk * 16 + akoff) * 2);
        #pragma unroll
        for (int g = 0; g < 4; g++) {
            // non-trans ldmatrix on W[n][k] -> col-major B frag:
            // r0 = n-blk0 k-lo, r1 = n-blk1 k-lo, r2 = n-blk0 k-hi, r3 = n-blk1 k-hi
            unsigned r[4];
            ldm_x4(r, sbase + OFF_W + (wn + g * 16 + arow) * RSB + (kk * 16 + akoff) * 2);
            b[2 * g][0] = r[0]; b[2 * g][1] = r[2];
            b[2 * g + 1][0] = r[1]; b[2 * g + 1][1] = r[3];
        }
        #pragma unroll
        for (int mb = 0; mb < 2; mb++)
            #pragma unroll
            for (int nb = 0; nb < 8; nb++)
                mma16816(acc[mb][nb], a[mb], b[nb]);
    }
}

// ---------------- persistent kernel ------------------------------------------
__global__ void __launch_bounds__(NTHR, 1) rnn_mma(
    const float* __restrict__ x, const float* __restrict__ h0,
    const float* __restrict__ W_ih, const float* __restrict__ W_hh,
    const float* __restrict__ b_ih, const float* __restrict__ b_hh,
    float* __restrict__ out)
{
    extern __shared__ __align__(16) char dsm[];

    const int tid = threadIdx.x;
    const int lane = tid & 31;
    const int w = tid >> 5;
    const int wm = (w >> 1) * 32;        // 4 warp-rows
    const int wn = (w & 1) * 64;         // 2 warp-cols
    const int cta = blockIdx.x;
    const int l = cta / 48;              // layer slot 0..2
    const int p = (cta / 16) % 3;        // product: 0=Ah*Wh 1=Al*Wh 2=Ah*Wl
    const int tile = cta % 16;
    const int m0 = (tile & 1) * 128;
    const int n0 = (tile >> 1) * 128;

    const unsigned dynu = smem_u32(dsm);

    // ---- prepass: split W / h0 / x0, bias sums ------------------------------
    for (int idx = cta * NTHR + tid; idx < LL * HH * KTOT; idx += GSTRIDE) {
        int l2 = idx >> 21;
        int rem = idx & ((1 << 21) - 1);
        int n = rem >> 11;
        int k2 = rem & (KTOT - 1);
        float f = (k2 < HH) ? W_ih[((size_t)l2 * HH + n) * HH + k2]
                            : W_hh[((size_t)l2 * HH + n) * HH + (k2 - HH)];
        split2(f, ((ush*)g_w_hi)[idx], ((ush*)g_w_lo)[idx]);
    }
    for (int idx = cta * NTHR + tid; idx < LL * BH; idx += GSTRIDE) {
        int l2 = idx >> 18;
        int i = idx & (BH - 1);
        split2(h0[idx], g_h_hi[l2][1][i], g_h_lo[l2][1][i]);
    }
    for (int idx = cta * NTHR + tid; idx < BH; idx += GSTRIDE)
        split2(x[idx], g_x_hi[0][idx], g_x_lo[0][idx]);
    for (int idx = cta * NTHR + tid; idx < LL * HH; idx += GSTRIDE)
        ((float*)g_bias)[idx] = b_ih[idx] + b_hh[idx];

    grid_barrier(1u);
    unsigned bt = 2;

    // per-CTA operand component pointers (fixed roles)
    const ush* wC = (p == 2) ? &g_w_lo[l][0][0] : &g_w_hi[l][0][0];

    for (int d = 0; d < SS + LL - 1; d++) {
        const int t = d - l;
        if (t >= 0 && t < SS) {
            const ush* inpC;
            const ush* prvC;
            if (p == 1) {   // A = lo component
                inpC = (l == 0) ? g_x_lo[t & 1] : g_h_lo[l - 1][t & 1];
                prvC = g_h_lo[l][(t & 1) ^ 1];
            } else {        // A = hi component
                inpC = (l == 0) ? g_x_hi[t & 1] : g_h_hi[l - 1][t & 1];
                prvC = g_h_hi[l][(t & 1) ^ 1];
            }

            float acc[2][8][4];
            #pragma unroll
            for (int a = 0; a < 2; a++)
                #pragma unroll
                for (int b = 0; b < 8; b++)
                    #pragma unroll
                    for (int cc = 0; cc < 4; cc++) acc[a][b][cc] = 0.f;

            // 3-stage cp.async ring, one barrier per chunk (R6-proven invariant)
            issue_loads(0, dynu + 0 * BUFSZ, tid, m0, n0, inpC, prvC, wC);
            cp_commit();
            issue_loads(1, dynu + 1 * BUFSZ, tid, m0, n0, inpC, prvC, wC);
            cp_commit();
            int bufc = 0;
            for (int c = 0; c < NCHUNK; c++) {
                if (c == NCHUNK - 1) cp_wait0(); else cp_wait1();
                __syncthreads();
                if (c + 2 < NCHUNK) {
                    int bufn = bufc + 2 - ((bufc + 2 >= NSTAGE) ? NSTAGE : 0);
                    issue_loads(c + 2, dynu + bufn * BUFSZ, tid, m0, n0, inpC, prvC, wC);
                    cp_commit();
                }
                compute_chunk(dynu + bufc * BUFSZ, lane, wm, wn, acc);
                if (++bufc == NSTAGE) bufc = 0;
            }

            // write fp32 partial tile to global scratch
            float* pd = &g_part[l][p][0];
            #pragma unroll
            for (int mb = 0; mb < 2; mb++) {
                #pragma unroll
                for (int rh = 0; rh < 2; rh++) {
                    const int gm = m0 + wm + mb * 16 + rh * 8 + (lane >> 2);
                    #pragma unroll
                    for (int nb = 0; nb < 8; nb++) {
                        const int gn = n0 + wn + nb * 8 + 2 * (lane & 3);
                        *(float2*)(pd + (size_t)gm * HH + gn) =
                            make_float2(acc[mb][nb][rh * 2 + 0], acc[mb][nb][rh * 2 + 1]);
                    }
                }
            }
        }
        grid_barrier(bt++);   // all partials of diagonal d visible

        // ---- combine phase: sum 3 partials + bias + tanh + split + store ----
        {
            const int NV = 3 * BH / 4;   // float4 units across the 3 stage slots
            for (int v = cta * NTHR + tid; v < NV; v += GSTRIDE) {
                const int s = v >> 16;           // BH/4 = 65536 per slot
                const int tt = d - s;
                if (tt < 0 || tt >= SS) continue;
                const int i = (v & 65535) * 4;
                const float4 p0 = *(const float4*)&g_part[s][0][i];
                const float4 p1 = *(const float4*)&g_part[s][1][i];
                const float4 p2 = *(const float4*)&g_part[s][2][i];
                const float4 bv = *(const float4*)&g_bias[s][i & 1023];
                float f[4];
                f[0] = tanhf(p0.x + p1.x + p2.x + bv.x);
                f[1] = tanhf(p0.y + p1.y + p2.y + bv.y);
                f[2] = tanhf(p0.z + p1.z + p2.z + bv.z);
                f[3] = tanhf(p0.w + p1.w + p2.w + bv.w);
                ush hu[4], lu[4];
                #pragma unroll
                for (int j = 0; j < 4; j++) split2(f[j], hu[j], lu[j]);
                *(uint2*)&g_h_hi[s][tt & 1][i] =
                    make_uint2((unsigned)hu[0] | ((unsigned)hu[1] << 16),
                               (unsigned)hu[2] | ((unsigned)hu[3] << 16));
                *(uint2*)&g_h_lo[s][tt & 1][i] =
                    make_uint2((unsigned)lu[0] | ((unsigned)lu[1] << 16),
                               (unsigned)lu[2] | ((unsigned)lu[3] << 16));
                if (s == LL - 1)
                    *(float4*)(out + (size_t)tt * BH + i) = make_float4(f[0], f[1], f[2], f[3]);
                if (tt == SS - 1)
                    *(float4*)(out + (size_t)SS * BH + (size_t)s * BH + i) =
                        make_float4(f[0], f[1], f[2], f[3]);
            }
            // split x_{d+1} into the other ring slot (read by diagonal d+1, layer 0)
            const int tn = d + 1;
            if (tn < SS) {
                const int sl = tn & 1;
                for (int i = cta * NTHR + tid; i < BH; i += GSTRIDE)
                    split2(x[(size_t)tn * BH + i], g_x_hi[sl][i], g_x_lo[sl][i]);
            }
        }
        grid_barrier(bt++);   // h/x ready for diagonal d+1
    }
}

extern "C" void kernel_launch(void* const* d_in, const int* in_sizes, int n_in,
                              void* d_out, int out_size) {
    const float* x    = (const float*)d_in[0];
    const float* h0   = (const float*)d_in[1];
    const float* W_ih = (const float*)d_in[2];
    const float* W_hh = (const float*)d_in[3];
    const float* b_ih = (const float*)d_in[4];
    const float* b_hh = (const float*)d_in[5];
    float* out = (float*)d_out;

    cudaFuncSetAttribute(rnn_mma, cudaFuncAttributeMaxDynamicSharedMemorySize, SMEM_DYN);
    void* sp = nullptr;
    cudaGetSymbolAddress(&sp, g_sync);
    cudaMemsetAsync(sp, 0, sizeof(unsigned) * 2);
    rnn_mma<<<NCTA, NTHR, SMEM_DYN>>>(x, h0, W_ih, W_hh, b_ih, b_hh, out);
}